// round 16
// baseline (speedup 1.0000x reference)
#include <cuda_runtime.h>
#include <cuda_fp16.h>
#include <cstdint>

#define IN_DIM   4096
#define OUT_DIM  16384
#define MDIM     32

#define NTILE    64             // output cols per CTA -> grid 256
#define KC       64             // K per chunk
#define NCHUNK   (IN_DIM / KC)  // 64
#define NST_ST   3              // staging ring (linear, 272B rows)
#define NST_A    4              // A ring (8KB SW128 stages)
#define K_PER_MMA 16
#define MMA_M    128
#define MMA_IDESC ((1u<<4) | ((NTILE/8)<<17) | ((MMA_M/16)<<24))   // f32 acc, f16 in

#define NTHREADS 288            // 8 producer warps + 1 MMA/TMA warp

#define ST_ROWB  272            // staging row stride (256 data + 16 pad)
#define ST_SIZE  (64 * ST_ROWB) // 17408 per stage

// ---- dynamic smem layout (bytes)
#define SM_TMEMPTR 0
#define SM_MBAR(s) (8 + 8*(s))                    // 0..3 mma_done, 4..5 full, 6..9 tmaB
#define SM_A(s)    (1024 + (s)*8192)              // 4 x 8KB fp16 A
#define SM_BF(s)   (33792 + (s)*8192)             // 2 x 8KB fp16 B
#define SM_ST(s)   (50176 + (s)*ST_SIZE)          // 3 x 17408 raw int32 staging
#define SMEM_TOTAL 102400                          // 100KB -> 2 CTAs/SM
// epilogue scratch reuses A region after drain
#define EP_OFF     1024                           // [32][33] floats
#define YS_OFF     (1024 + 4352)                  // [32][68] floats

// arch-specific gate: tcgen05 only exists in the sm_103a-specific target.
#if defined(__CUDA_ARCH_FEAT_SM103_ALL) || defined(__CUDA_ARCH_FEAT_SM100_ALL) || \
    defined(__CUDA_ARCH_FEAT_SM101_ALL) || \
    (defined(__CUDA_ARCH_SPECIFIC__)) || (defined(__CUDA_ARCH_FAMILY_SPECIFIC__))
#define TC_OK 1
#else
#define TC_OK 0
#endif

// pre-converted A: rows 0..31 = hi(x), rows 32..63 = lo(x), fp16, row-major [64][4096]
__device__ __align__(1024) __half g_A[64 * IN_DIM];

#define SW128(o) ((o) ^ (((o) >> 3) & 0x70))

#if TC_OK
__device__ __forceinline__ uint32_t elect1() {
    uint32_t p;
    asm volatile("{\n\t.reg .pred p;\n\telect.sync _|p, 0xFFFFFFFF;\n\tselp.b32 %0, 1, 0, p;\n\t}" : "=r"(p));
    return p;
}

__device__ __forceinline__ void mma_f16_ss(uint32_t d_tmem, uint64_t a_desc,
                                           uint64_t b_desc, uint32_t idesc, uint32_t en) {
    asm volatile(
        "{\n\t.reg .pred p;\n\tsetp.ne.u32 p, %4, 0;\n\t"
        "tcgen05.mma.cta_group::1.kind::f16 [%0], %1, %2, %3, {%5, %5, %5, %5}, p;\n\t}"
        :: "r"(d_tmem), "l"(a_desc), "l"(b_desc), "r"(idesc), "r"(en), "r"(0u)
        : "memory");
}

// K-major SW128 smem descriptor (LBO=1, SBO=64, version=1, layout=SW128)
__device__ __forceinline__ uint64_t mk_desc(uint32_t saddr) {
    return ((uint64_t)2 << 61) | ((uint64_t)1 << 46) | ((uint64_t)64 << 32)
         | ((uint64_t)1 << 16) | ((uint64_t)(saddr >> 4) & 0x3FFF);
}

__device__ __forceinline__ void mbar_wait(uint32_t mb, int phase) {
    uint32_t done;
    asm volatile(
        "{\n\t.reg .pred p;\n\t"
        "mbarrier.try_wait.parity.acquire.cta.shared::cta.b64 p, [%1], %2;\n\t"
        "selp.b32 %0, 1, 0, p;\n\t}" : "=r"(done) : "r"(mb), "r"(phase) : "memory");
    if (!done) {
        asm volatile(
            "{\n\t.reg .pred P1;\n\tW0_%=:\n\t"
            "mbarrier.try_wait.parity.acquire.cta.shared::cta.b64 P1, [%0], %1, 0x989680;\n\t"
            "@P1 bra.uni W1_%=;\n\tbra.uni W0_%=;\n\tW1_%=:\n\t}"
            :: "r"(mb), "r"(phase) : "memory");
    }
}

__device__ __forceinline__ void cp16(uint32_t dst, const void* src) {
    asm volatile("cp.async.cg.shared.global [%0], [%1], 16;"
                 :: "r"(dst), "l"(src) : "memory");
}

__device__ __forceinline__ void bulk256(uint32_t dst, const void* src, uint32_t mbar) {
    asm volatile(
        "cp.async.bulk.shared::cta.global.mbarrier::complete_tx::bytes [%0], [%1], 256, [%2];"
        :: "r"(dst), "l"(src), "r"(mbar) : "memory");
}

// pack two int codes (0..255, high bytes zero) -> fp16x2 (q+1024), then subtract (1024+zero)
__device__ __forceinline__ uint32_t pack2(uint32_t a, uint32_t b, uint32_t hz2) {
    uint32_t r;
    asm("prmt.b32 %0, %1, %2, 0x5410;" : "=r"(r) : "r"(a), "r"(b));
    r += 0x64006400u;
    uint32_t o;
    asm("add.f16x2 %0, %1, %2;" : "=r"(o) : "r"(r), "r"(hz2));
    return o;
}
#endif

__global__ void xsplit_kernel(const float* __restrict__ x) {
    int i = blockIdx.x * blockDim.x + threadIdx.x;   // 0 .. 32*4096-1
    if (i >= MDIM * IN_DIM) return;
    float v  = x[i];
    __half h = __float2half_rn(v);
    __half l = __float2half_rn(v - __half2float(h));
    int m = i / IN_DIM, k = i % IN_DIM;
    g_A[m * IN_DIM + k]        = h;
    g_A[(m + 32) * IN_DIM + k] = l;
}

__global__ __launch_bounds__(NTHREADS, 2)
void qgemm_tc(const int* __restrict__ wq,
              const int* __restrict__ zerop,
              const float* __restrict__ scalep,
              const float* __restrict__ bias,
              float* __restrict__ out)
{
#if TC_OK
    extern __shared__ char smem[];
    const uint32_t sb = (uint32_t)__cvta_generic_to_shared(smem);
    const int t   = threadIdx.x;
    const int wid = t >> 5;
    const int lid = t & 31;
    const int o0  = blockIdx.x * NTILE;

    const int zero = zerop[0];
    const __half  hzh = __int2half_rn(-1024 - zero);
    const __half2 hzv = __halves2half2(hzh, hzh);
    const uint32_t hz2 = *(const uint32_t*)&hzv;

    if (wid == 0) {
        asm volatile("tcgen05.alloc.cta_group::1.sync.aligned.shared::cta.b32 [%0], %1;"
                     :: "r"(sb + SM_TMEMPTR), "r"(64u) : "memory");
        asm volatile("tcgen05.relinquish_alloc_permit.cta_group::1.sync.aligned;");
    }
    if (t == 0) {
#pragma unroll
        for (int s = 0; s < 4; s++)    // mma-commit mbars, count 1
            asm volatile("mbarrier.init.shared.b64 [%0], 1;" :: "r"(sb + SM_MBAR(s)) : "memory");
#pragma unroll
        for (int s = 4; s < 6; s++)    // full mbars, count 8 (one per producer warp)
            asm volatile("mbarrier.init.shared.b64 [%0], 8;" :: "r"(sb + SM_MBAR(s)) : "memory");
#pragma unroll
        for (int s = 6; s < 10; s++)   // tmaB mbars, count 1 (expect_tx arrive)
            asm volatile("mbarrier.init.shared.b64 [%0], 1;" :: "r"(sb + SM_MBAR(s)) : "memory");
    }
    __syncthreads();
    uint32_t tmem;
    asm volatile("ld.shared.b32 %0, [%1];" : "=r"(tmem) : "r"(sb + SM_TMEMPTR));

    if (wid < 8) {
        // ================= PRODUCER WARPS (convert + A feed) =================
        // convert map: row group rg = t>>4 (4 rows each), s16 = t&15 (16B col segment)
        const int s16 = t & 15, rg = t >> 4;
        // A: row ar = t>>2 (0..63), seg as = t&3 (32B); 2x16B cp.async, SW128
        const int ar = t >> 2, as = t & 3;
        const char* asrc = (const char*)g_A + (size_t)ar * IN_DIM * 2 + as * 32;
        const uint32_t a_sw0 = SW128((uint32_t)(ar*128 + as*32));
        const uint32_t a_sw1 = SW128((uint32_t)(ar*128 + as*32 + 16));

#define CPA(c)                                                                    \
    do {                                                                          \
        const uint32_t atile = sb + SM_A((c) & (NST_A - 1));                      \
        cp16(atile + a_sw0, asrc + (size_t)(c) * 128);                            \
        cp16(atile + a_sw1, asrc + (size_t)(c) * 128 + 16);                       \
        asm volatile("cp.async.commit_group;" ::: "memory");                      \
    } while (0)

        int ph[4]   = {0, 0, 0, 0};   // mma_done phases
        int ph_t[4] = {0, 0, 0, 0};   // tmaB phases

        CPA(0);
        CPA(1);

        for (int c = 0; c < NCHUNK; c++) {
            // gate BF(c&1) + A stage (c+2)&3 reuse on MMA(c-2) completion
            if (c >= 2) {
                const int b = (c - 2) & 3;
                mbar_wait(sb + SM_MBAR(b), ph[b]);
                ph[b] ^= 1;
            }

            if (c + 2 < NCHUNK) CPA(c + 2);

            // A(c) landed (A-only groups; up to 2 newer pending)
            if (c + 2 < NCHUNK)
                asm volatile("cp.async.wait_group 2;" ::: "memory");
            else if (c + 1 < NCHUNK)
                asm volatile("cp.async.wait_group 1;" ::: "memory");
            else
                asm volatile("cp.async.wait_group 0;" ::: "memory");

            // B staging for chunk c arrived (bulk copies issued by MMA warp)
            {
                const int m = c & 3;
                mbar_wait(sb + SM_MBAR(6 + m), ph_t[m]);
                ph_t[m] ^= 1;
            }

            // convert staging (linear 272B rows) -> fp16 B tile (SW128)
            {
                const uint32_t stg = sb + SM_ST(c % NST_ST);
                const uint32_t bf  = sb + SM_BF(c & 1);
#pragma unroll
                for (int j = 0; j < 4; j++) {
                    const int row = rg * 4 + j;
                    uint4 q4;
                    asm volatile("ld.shared.v4.b32 {%0,%1,%2,%3}, [%4];"
                        : "=r"(q4.x), "=r"(q4.y), "=r"(q4.z), "=r"(q4.w)
                        : "r"(stg + (uint32_t)(row * ST_ROWB + s16 * 16)));
                    uint32_t h0 = pack2((uint32_t)q4.x, (uint32_t)q4.y, hz2);
                    uint32_t h1 = pack2((uint32_t)q4.z, (uint32_t)q4.w, hz2);
                    uint32_t off = SW128((uint32_t)(row * 128 + s16 * 8));
                    asm volatile("st.shared.v2.b32 [%0], {%1,%2};"
                        :: "r"(bf + off), "r"(h0), "r"(h1) : "memory");
                }
            }

            // signal: this warp's slice of chunk c ready
            asm volatile("fence.proxy.async.shared::cta;" ::: "memory");
            __syncwarp();
            if (elect1())
                asm volatile("mbarrier.arrive.shared.b64 _, [%0];"
                             :: "r"(sb + SM_MBAR(4 + (c & 1))) : "memory");
        }

        // drain: MMAs of chunks 62, 63 (needed before epilogue TMEM read)
        {
            const int bA = (NCHUNK - 2) & 3;
            mbar_wait(sb + SM_MBAR(bA), ph[bA]);
            const int bB = (NCHUNK - 1) & 3;
            mbar_wait(sb + SM_MBAR(bB), ph[bB]);
        }
        asm volatile("tcgen05.fence::after_thread_sync;" ::: "memory");
    } else {
        // ================= MMA + TMA WARP (wid == 8) =================
        // lanes issue 2 bulk B-row copies each (rows 2*lid, 2*lid+1)
        const int r0 = 2 * lid, r1 = 2 * lid + 1;
        const char* bs0 = (const char*)(wq + (size_t)(o0 + r0) * IN_DIM);
        const char* bs1 = (const char*)(wq + (size_t)(o0 + r1) * IN_DIM);

#define TMAB(c)                                                                   \
    do {                                                                          \
        const uint32_t mb  = sb + SM_MBAR(6 + ((c) & 3));                         \
        const uint32_t stg = sb + SM_ST((c) % NST_ST);                            \
        if (elect1())                                                             \
            asm volatile("mbarrier.arrive.expect_tx.shared.b64 _, [%0], 16384;"   \
                         :: "r"(mb) : "memory");                                  \
        bulk256(stg + (uint32_t)(r0 * ST_ROWB), bs0 + (size_t)(c) * 256, mb);     \
        bulk256(stg + (uint32_t)(r1 * ST_ROWB), bs1 + (size_t)(c) * 256, mb);     \
    } while (0)

        TMAB(0);
        TMAB(1);

        int phf[2] = {0, 0};
        for (int c = 0; c < NCHUNK; c++) {
            const int f = c & 1;
            mbar_wait(sb + SM_MBAR(4 + f), phf[f]);
            phf[f] ^= 1;
            if (elect1()) {
                // A desc footprint rows 64..127 read junk (adjacent region) -> only
                // pollutes D rows 64..127, never read out.
                uint64_t ad = mk_desc(sb + SM_A(c & (NST_A - 1)));
                uint64_t bd = mk_desc(sb + SM_BF(f));
#pragma unroll
                for (int s = 0; s < KC / K_PER_MMA; s++)
                    mma_f16_ss(tmem, ad + s * 2, bd + s * 2, MMA_IDESC,
                               (c > 0 || s > 0) ? 1u : 0u);
                asm volatile(
                    "tcgen05.commit.cta_group::1.mbarrier::arrive::one.shared::cluster.b64 [%0];"
                    :: "r"(sb + SM_MBAR(c & 3)) : "memory");
            }
            // issue B bulk loads for chunk c+2; staging stage (c+2)%3 = (c-1)%3
            // was consumed during chunk c-1 (full(c-1) observed before MMA(c-1)).
            if (c + 2 < NCHUNK) TMAB(c + 2);
        }
    }

    __syncthreads();   // converge all 9 warps; A region reused as epilogue scratch

    // ---- epilogue: warp0 holds hi rows (m=lid), warp1 holds lo rows
    const float scale = scalep[0];
    float* Ep = (float*)(smem + EP_OFF);     // [32][33]
    float* Ys = (float*)(smem + YS_OFF);     // [32][68]

    for (int s = 0; s < 2; s++) {
        uint32_t d[32];
        if (wid < 2) {
            asm volatile(
                "tcgen05.ld.sync.aligned.32x32b.x32.b32 "
                "{%0,%1,%2,%3,%4,%5,%6,%7,%8,%9,%10,%11,%12,%13,%14,%15,"
                "%16,%17,%18,%19,%20,%21,%22,%23,%24,%25,%26,%27,%28,%29,%30,%31}, [%32];"
                : "=r"(d[0]), "=r"(d[1]), "=r"(d[2]), "=r"(d[3]), "=r"(d[4]), "=r"(d[5]),
                  "=r"(d[6]), "=r"(d[7]), "=r"(d[8]), "=r"(d[9]), "=r"(d[10]), "=r"(d[11]),
                  "=r"(d[12]), "=r"(d[13]), "=r"(d[14]), "=r"(d[15]), "=r"(d[16]), "=r"(d[17]),
                  "=r"(d[18]), "=r"(d[19]), "=r"(d[20]), "=r"(d[21]), "=r"(d[22]), "=r"(d[23]),
                  "=r"(d[24]), "=r"(d[25]), "=r"(d[26]), "=r"(d[27]), "=r"(d[28]), "=r"(d[29]),
                  "=r"(d[30]), "=r"(d[31])
                : "r"(tmem + s * 32));
            asm volatile("tcgen05.wait::ld.sync.aligned;" ::: "memory");
        }
        if (wid == 1) {
#pragma unroll
            for (int cc = 0; cc < 32; cc++) Ep[lid * 33 + cc] = __uint_as_float(d[cc]);
        }
        __syncthreads();
        if (wid == 0) {
#pragma unroll
            for (int cc = 0; cc < 32; cc++) {
                float hi = __uint_as_float(d[cc]);
                float lo = Ep[lid * 33 + cc];
                float b  = bias[o0 + s * 32 + cc];
                Ys[lid * 68 + s * 32 + cc] = fmaf(scale, hi + lo, b);
            }
        }
        __syncthreads();
    }

    // ---- coalesced store: 32 rows x 64 cols (first 256 threads)
    if (t < 256) {
        const int m = t >> 3, q8 = t & 7;
#pragma unroll
        for (int i = 0; i < 2; i++) {
            const int qq = q8 + 8 * i;
            float4 v = *(const float4*)(Ys + m * 68 + qq * 4);
            *(float4*)(out + (size_t)m * OUT_DIM + o0 + qq * 4) = v;
        }
    }

    __syncthreads();
    if (t == 0) {
#pragma unroll
        for (int s = 0; s < 10; s++)
            asm volatile("mbarrier.inval.shared.b64 [%0];" :: "r"(sb + SM_MBAR(s)) : "memory");
    }
    __syncthreads();
    if (wid == 0) {
        asm volatile("tcgen05.dealloc.cta_group::1.sync.aligned.b32 %0, %1;"
                     :: "r"(tmem), "r"(64u));
    }
#endif  // TC_OK
}

extern "C" void kernel_launch(void* const* d_in, const int* in_sizes, int n_in,
                              void* d_out, int out_size)
{
    const float* x     = (const float*)d_in[0];
    const int*   wq    = (const int*)  d_in[1];
    const int*   zero  = (const int*)  d_in[2];
    const float* scale = (const float*)d_in[3];
    const float* bias  = (const float*)d_in[4];
    float*       out   = (float*)d_out;

    cudaFuncSetAttribute(qgemm_tc, cudaFuncAttributeMaxDynamicSharedMemorySize, SMEM_TOTAL);

    xsplit_kernel<<<(MDIM * IN_DIM + 255) / 256, 256>>>(x);
    qgemm_tc<<<OUT_DIM / NTILE, NTHREADS, SMEM_TOTAL>>>(wq, zero, scale, bias, out);
}

// round 17
// speedup vs baseline: 2.3836x; 2.3836x over previous
#include <cuda_runtime.h>
#include <cuda.h>
#include <cuda_fp16.h>
#include <cstdint>

#define IN_DIM   4096
#define OUT_DIM  16384
#define MDIM     32

#define NTILE    64             // output cols per CTA -> grid 256
#define KC       64             // K per chunk
#define NCHUNK   (IN_DIM / KC)  // 64
#define NST_ST   3              // B staging ring (two 8KB SW128 sub-tiles per stage)
#define NST_A    4              // A ring (8KB SW128 stages)
#define K_PER_MMA 16
#define MMA_M    128
#define MMA_IDESC ((1u<<4) | ((NTILE/8)<<17) | ((MMA_M/16)<<24))   // f32 acc, f16 in

#define NTHREADS 288            // 8 producer warps + 1 MMA/TMA warp

// ---- dynamic smem layout (bytes)
#define SM_TMEMPTR 0
#define SM_MBAR(s) (8 + 8*(s))                    // 0..3 mma_done, 4..5 full, 6..9 tma
#define SM_A(s)    (1024 + (s)*8192)              // 4 x 8KB fp16 A (SW128, TMA-filled)
#define SM_BF(s)   (33792 + (s)*8192)             // 2 x 8KB fp16 B
#define SM_ST(s)   (50176 + (s)*16384)            // 3 x 16KB int32 staging (SW128, TMA)
#define SMEM_TOTAL 99328                          // 97KB -> 2 CTAs/SM
// epilogue scratch reuses A region after drain
#define EP_OFF     1024                           // [32][33] floats
#define YS_OFF     (1024 + 4352)                  // [32][68] floats

// arch-specific gate: tcgen05 only exists in the sm_103a-specific target.
#if defined(__CUDA_ARCH_FEAT_SM103_ALL) || defined(__CUDA_ARCH_FEAT_SM100_ALL) || \
    defined(__CUDA_ARCH_FEAT_SM101_ALL) || \
    (defined(__CUDA_ARCH_SPECIFIC__)) || (defined(__CUDA_ARCH_FAMILY_SPECIFIC__))
#define TC_OK 1
#else
#define TC_OK 0
#endif

// pre-converted A: rows 0..31 = hi(x), rows 32..63 = lo(x), fp16, row-major [64][4096]
__device__ __align__(1024) __half g_A[64 * IN_DIM];

#define SW128(o) ((o) ^ (((o) >> 3) & 0x70))

#if TC_OK
__device__ __forceinline__ uint32_t elect1() {
    uint32_t p;
    asm volatile("{\n\t.reg .pred p;\n\telect.sync _|p, 0xFFFFFFFF;\n\tselp.b32 %0, 1, 0, p;\n\t}" : "=r"(p));
    return p;
}

__device__ __forceinline__ void mma_f16_ss(uint32_t d_tmem, uint64_t a_desc,
                                           uint64_t b_desc, uint32_t idesc, uint32_t en) {
    asm volatile(
        "{\n\t.reg .pred p;\n\tsetp.ne.u32 p, %4, 0;\n\t"
        "tcgen05.mma.cta_group::1.kind::f16 [%0], %1, %2, %3, {%5, %5, %5, %5}, p;\n\t}"
        :: "r"(d_tmem), "l"(a_desc), "l"(b_desc), "r"(idesc), "r"(en), "r"(0u)
        : "memory");
}

// K-major SW128 smem descriptor (LBO=1, SBO=64, version=1, layout=SW128)
__device__ __forceinline__ uint64_t mk_desc(uint32_t saddr) {
    return ((uint64_t)2 << 61) | ((uint64_t)1 << 46) | ((uint64_t)64 << 32)
         | ((uint64_t)1 << 16) | ((uint64_t)(saddr >> 4) & 0x3FFF);
}

__device__ __forceinline__ void mbar_wait(uint32_t mb, int phase) {
    uint32_t done;
    asm volatile(
        "{\n\t.reg .pred p;\n\t"
        "mbarrier.try_wait.parity.acquire.cta.shared::cta.b64 p, [%1], %2;\n\t"
        "selp.b32 %0, 1, 0, p;\n\t}" : "=r"(done) : "r"(mb), "r"(phase) : "memory");
    if (!done) {
        asm volatile(
            "{\n\t.reg .pred P1;\n\tW0_%=:\n\t"
            "mbarrier.try_wait.parity.acquire.cta.shared::cta.b64 P1, [%0], %1, 0x989680;\n\t"
            "@P1 bra.uni W1_%=;\n\tbra.uni W0_%=;\n\tW1_%=:\n\t}"
            :: "r"(mb), "r"(phase) : "memory");
    }
}

__device__ __forceinline__ void tma2d(uint32_t dst, const CUtensorMap* tm,
                                      int x, int y, uint32_t mbar) {
    asm volatile(
        "cp.async.bulk.tensor.2d.shared::cta.global.tile.mbarrier::complete_tx::bytes "
        "[%0], [%1, {%2, %3}], [%4];"
        :: "r"(dst), "l"(tm), "r"(x), "r"(y), "r"(mbar) : "memory");
}

// pack two int codes (0..255, high bytes zero) -> fp16x2 (q+1024), then subtract (1024+zero)
__device__ __forceinline__ uint32_t pack2(uint32_t a, uint32_t b, uint32_t hz2) {
    uint32_t r;
    asm("prmt.b32 %0, %1, %2, 0x5410;" : "=r"(r) : "r"(a), "r"(b));
    r += 0x64006400u;
    uint32_t o;
    asm("add.f16x2 %0, %1, %2;" : "=r"(o) : "r"(r), "r"(hz2));
    return o;
}
#endif

__global__ void xsplit_kernel(const float* __restrict__ x) {
    int i = blockIdx.x * blockDim.x + threadIdx.x;   // 0 .. 32*4096-1
    if (i >= MDIM * IN_DIM) return;
    float v  = x[i];
    __half h = __float2half_rn(v);
    __half l = __float2half_rn(v - __half2float(h));
    int m = i / IN_DIM, k = i % IN_DIM;
    g_A[m * IN_DIM + k]        = h;
    g_A[(m + 32) * IN_DIM + k] = l;
}

__global__ __launch_bounds__(NTHREADS, 2)
void qgemm_tc(const __grid_constant__ CUtensorMap tmA,
              const __grid_constant__ CUtensorMap tmB,
              const int* __restrict__ zerop,
              const float* __restrict__ scalep,
              const float* __restrict__ bias,
              float* __restrict__ out)
{
#if TC_OK
    extern __shared__ char smem[];
    const uint32_t sb = (uint32_t)__cvta_generic_to_shared(smem);
    const int t   = threadIdx.x;
    const int wid = t >> 5;
    const int lid = t & 31;
    const int o0  = blockIdx.x * NTILE;

    const int zero = zerop[0];
    const __half  hzh = __int2half_rn(-1024 - zero);
    const __half2 hzv = __halves2half2(hzh, hzh);
    const uint32_t hz2 = *(const uint32_t*)&hzv;

    if (wid == 0) {
        asm volatile("tcgen05.alloc.cta_group::1.sync.aligned.shared::cta.b32 [%0], %1;"
                     :: "r"(sb + SM_TMEMPTR), "r"(64u) : "memory");
        asm volatile("tcgen05.relinquish_alloc_permit.cta_group::1.sync.aligned;");
    }
    if (t == 0) {
#pragma unroll
        for (int s = 0; s < 4; s++)    // mma-commit mbars, count 1
            asm volatile("mbarrier.init.shared.b64 [%0], 1;" :: "r"(sb + SM_MBAR(s)) : "memory");
#pragma unroll
        for (int s = 4; s < 6; s++)    // full mbars, count 8
            asm volatile("mbarrier.init.shared.b64 [%0], 8;" :: "r"(sb + SM_MBAR(s)) : "memory");
#pragma unroll
        for (int s = 6; s < 10; s++)   // tma mbars, count 1 (expect_tx)
            asm volatile("mbarrier.init.shared.b64 [%0], 1;" :: "r"(sb + SM_MBAR(s)) : "memory");
    }
    __syncthreads();
    uint32_t tmem;
    asm volatile("ld.shared.b32 %0, [%1];" : "=r"(tmem) : "r"(sb + SM_TMEMPTR));

    if (wid < 8) {
        // ================= PRODUCER WARPS (convert only) =================
        // map: row r = t>>2 (0..63), quarter qo = t&3 (32B of each 128B sub-row)
        const int r = t >> 2, qo = t & 3;
        const uint32_t l_off0 = SW128((uint32_t)(r*128 + qo*32));
        const uint32_t l_off1 = SW128((uint32_t)(r*128 + qo*32 + 16));

        int ph[4]   = {0, 0, 0, 0};   // mma_done phases
        int ph_t[4] = {0, 0, 0, 0};   // tma phases

        for (int c = 0; c < NCHUNK; c++) {
            // BF(c&1) write safety: MMA(c-2) (which read it) must be done
            if (c >= 2) {
                const int b = (c - 2) & 3;
                mbar_wait(sb + SM_MBAR(b), ph[b]);
                ph[b] ^= 1;
            }
            // staging(c%3) + A(c&3) arrived
            {
                const int m = c & 3;
                mbar_wait(sb + SM_MBAR(6 + m), ph_t[m]);
                ph_t[m] ^= 1;
            }

            // convert SW128 int32 staging -> SW128 fp16 B tile
            {
                const uint32_t stg = sb + SM_ST(c % NST_ST);
                const uint32_t bf  = sb + SM_BF(c & 1);
#pragma unroll
                for (int s2 = 0; s2 < 2; s2++) {
                    const uint32_t src = stg + s2 * 8192;
                    uint4 a, b;
                    asm volatile("ld.shared.v4.b32 {%0,%1,%2,%3}, [%4];"
                        : "=r"(a.x), "=r"(a.y), "=r"(a.z), "=r"(a.w) : "r"(src + l_off0));
                    asm volatile("ld.shared.v4.b32 {%0,%1,%2,%3}, [%4];"
                        : "=r"(b.x), "=r"(b.y), "=r"(b.z), "=r"(b.w) : "r"(src + l_off1));
                    uint32_t h0 = pack2(a.x, a.y, hz2);
                    uint32_t h1 = pack2(a.z, a.w, hz2);
                    uint32_t h2 = pack2(b.x, b.y, hz2);
                    uint32_t h3 = pack2(b.z, b.w, hz2);
                    uint32_t doff = SW128((uint32_t)(r*128 + s2*64 + qo*16));
                    asm volatile("st.shared.v4.b32 [%0], {%1,%2,%3,%4};"
                        :: "r"(bf + doff), "r"(h0), "r"(h1), "r"(h2), "r"(h3) : "memory");
                }
            }

            asm volatile("fence.proxy.async.shared::cta;" ::: "memory");
            __syncwarp();
            if (elect1())
                asm volatile("mbarrier.arrive.shared.b64 _, [%0];"
                             :: "r"(sb + SM_MBAR(4 + (c & 1))) : "memory");
        }

        // drain: MMAs of chunks 62, 63
        {
            const int bA = (NCHUNK - 2) & 3;
            mbar_wait(sb + SM_MBAR(bA), ph[bA]);
            const int bB = (NCHUNK - 1) & 3;
            mbar_wait(sb + SM_MBAR(bB), ph[bB]);
        }
        asm volatile("tcgen05.fence::after_thread_sync;" ::: "memory");
    } else {
        // ================= MMA + TMA WARP (wid == 8) =================
#define TMAC(c)                                                                   \
    do {                                                                          \
        const uint32_t mb  = sb + SM_MBAR(6 + ((c) & 3));                         \
        const uint32_t stg = sb + SM_ST((c) % NST_ST);                            \
        const uint32_t atl = sb + SM_A((c) & (NST_A - 1));                        \
        asm volatile("mbarrier.arrive.expect_tx.shared.b64 _, [%0], 24576;"       \
                     :: "r"(mb) : "memory");                                      \
        tma2d(stg,        &tmB, (c) * 256,       o0, mb);                         \
        tma2d(stg + 8192, &tmB, (c) * 256 + 128, o0, mb);                         \
        tma2d(atl,        &tmA, (c) * 128,       0,  mb);                         \
    } while (0)

        if (elect1()) { TMAC(0); TMAC(1); TMAC(2); }

        int phf[2]  = {0, 0};
        int ph_d[4] = {0, 0, 0, 0};
        for (int c = 0; c < NCHUNK; c++) {
            const int f = c & 1;
            mbar_wait(sb + SM_MBAR(4 + f), phf[f]);
            phf[f] ^= 1;
            if (elect1()) {
                // A desc footprint rows 64..127 read junk (adjacent stage) -> only
                // pollutes D rows 64..127, never read out.
                uint64_t ad = mk_desc(sb + SM_A(c & (NST_A - 1)));
                uint64_t bd = mk_desc(sb + SM_BF(f));
#pragma unroll
                for (int s = 0; s < KC / K_PER_MMA; s++)
                    mma_f16_ss(tmem, ad + s * 2, bd + s * 2, MMA_IDESC,
                               (c > 0 || s > 0) ? 1u : 0u);
                asm volatile(
                    "tcgen05.commit.cta_group::1.mbarrier::arrive::one.shared::cluster.b64 [%0];"
                    :: "r"(sb + SM_MBAR(c & 3)) : "memory");
            }
            if (c + 3 < NCHUNK) {
                // A stage (c+3)&3 == (c-1)&3: MMA(c-1) must be done (in-order completion)
                if (c >= 1) {
                    const int d = (c - 1) & 3;
                    mbar_wait(sb + SM_MBAR(d), ph_d[d]);
                    ph_d[d] ^= 1;
                }
                // staging (c+3)%3 == (c)%3: consumed — full(c) already observed above
                if (elect1()) TMAC(c + 3);
            }
        }
    }

    __syncthreads();   // converge all 9 warps; A region reused as epilogue scratch

    // ---- epilogue: warp0 holds hi rows (m=lid), warp1 holds lo rows
    const float scale = scalep[0];
    float* Ep = (float*)(smem + EP_OFF);     // [32][33]
    float* Ys = (float*)(smem + YS_OFF);     // [32][68]

    for (int s = 0; s < 2; s++) {
        uint32_t d[32];
        if (wid < 2) {
            asm volatile(
                "tcgen05.ld.sync.aligned.32x32b.x32.b32 "
                "{%0,%1,%2,%3,%4,%5,%6,%7,%8,%9,%10,%11,%12,%13,%14,%15,"
                "%16,%17,%18,%19,%20,%21,%22,%23,%24,%25,%26,%27,%28,%29,%30,%31}, [%32];"
                : "=r"(d[0]), "=r"(d[1]), "=r"(d[2]), "=r"(d[3]), "=r"(d[4]), "=r"(d[5]),
                  "=r"(d[6]), "=r"(d[7]), "=r"(d[8]), "=r"(d[9]), "=r"(d[10]), "=r"(d[11]),
                  "=r"(d[12]), "=r"(d[13]), "=r"(d[14]), "=r"(d[15]), "=r"(d[16]), "=r"(d[17]),
                  "=r"(d[18]), "=r"(d[19]), "=r"(d[20]), "=r"(d[21]), "=r"(d[22]), "=r"(d[23]),
                  "=r"(d[24]), "=r"(d[25]), "=r"(d[26]), "=r"(d[27]), "=r"(d[28]), "=r"(d[29]),
                  "=r"(d[30]), "=r"(d[31])
                : "r"(tmem + s * 32));
            asm volatile("tcgen05.wait::ld.sync.aligned;" ::: "memory");
        }
        if (wid == 1) {
#pragma unroll
            for (int cc = 0; cc < 32; cc++) Ep[lid * 33 + cc] = __uint_as_float(d[cc]);
        }
        __syncthreads();
        if (wid == 0) {
#pragma unroll
            for (int cc = 0; cc < 32; cc++) {
                float hi = __uint_as_float(d[cc]);
                float lo = Ep[lid * 33 + cc];
                float b  = bias[o0 + s * 32 + cc];
                Ys[lid * 68 + s * 32 + cc] = fmaf(scale, hi + lo, b);
            }
        }
        __syncthreads();
    }

    // ---- coalesced store: 32 rows x 64 cols (first 256 threads)
    if (t < 256) {
        const int m = t >> 3, q8 = t & 7;
#pragma unroll
        for (int i = 0; i < 2; i++) {
            const int qq = q8 + 8 * i;
            float4 v = *(const float4*)(Ys + m * 68 + qq * 4);
            *(float4*)(out + (size_t)m * OUT_DIM + o0 + qq * 4) = v;
        }
    }

    __syncthreads();
    if (t == 0) {
#pragma unroll
        for (int s = 0; s < 10; s++)
            asm volatile("mbarrier.inval.shared.b64 [%0];" :: "r"(sb + SM_MBAR(s)) : "memory");
    }
    __syncthreads();
    if (wid == 0) {
        asm volatile("tcgen05.dealloc.cta_group::1.sync.aligned.b32 %0, %1;"
                     :: "r"(tmem), "r"(64u));
    }
#endif  // TC_OK
}

typedef CUresult (*PFN_tmEncode)(
    CUtensorMap*, CUtensorMapDataType, cuuint32_t, void*,
    const cuuint64_t*, const cuuint64_t*, const cuuint32_t*, const cuuint32_t*,
    CUtensorMapInterleave, CUtensorMapSwizzle, CUtensorMapL2promotion,
    CUtensorMapFloatOOBfill);

extern "C" void kernel_launch(void* const* d_in, const int* in_sizes, int n_in,
                              void* d_out, int out_size)
{
    const float* x     = (const float*)d_in[0];
    const int*   wq    = (const int*)  d_in[1];
    const int*   zero  = (const int*)  d_in[2];
    const float* scale = (const float*)d_in[3];
    const float* bias  = (const float*)d_in[4];
    float*       out   = (float*)d_out;

    static PFN_tmEncode tmEncode = nullptr;
    if (!tmEncode) {
        cudaDriverEntryPointQueryResult qr;
        void* fn = nullptr;
        cudaGetDriverEntryPoint("cuTensorMapEncodeTiled", &fn,
                                cudaEnableDefault, &qr);
        tmEncode = (PFN_tmEncode)fn;
    }

    void* gA_ptr = nullptr;
    cudaGetSymbolAddress(&gA_ptr, g_A);

    CUtensorMap tmA{}, tmB{};
    {   // A: uint8 view of g_A [64 rows x 8192 B], box 128B x 64 rows, SW128
        cuuint64_t dims[2]    = { (cuuint64_t)(IN_DIM * 2), 64 };
        cuuint64_t strides[1] = { (cuuint64_t)(IN_DIM * 2) };
        cuuint32_t box[2]     = { 128, 64 };
        cuuint32_t es[2]      = { 1, 1 };
        tmEncode(&tmA, CU_TENSOR_MAP_DATA_TYPE_UINT8, 2, gA_ptr,
                 dims, strides, box, es,
                 CU_TENSOR_MAP_INTERLEAVE_NONE, CU_TENSOR_MAP_SWIZZLE_128B,
                 CU_TENSOR_MAP_L2_PROMOTION_L2_128B, CU_TENSOR_MAP_FLOAT_OOB_FILL_NONE);
    }
    {   // B: uint8 view of wq [16384 rows x 16384 B], box 128B x 64 rows, SW128
        cuuint64_t dims[2]    = { (cuuint64_t)(IN_DIM * 4), OUT_DIM };
        cuuint64_t strides[1] = { (cuuint64_t)(IN_DIM * 4) };
        cuuint32_t box[2]     = { 128, 64 };
        cuuint32_t es[2]      = { 1, 1 };
        tmEncode(&tmB, CU_TENSOR_MAP_DATA_TYPE_UINT8, 2, (void*)wq,
                 dims, strides, box, es,
                 CU_TENSOR_MAP_INTERLEAVE_NONE, CU_TENSOR_MAP_SWIZZLE_128B,
                 CU_TENSOR_MAP_L2_PROMOTION_L2_128B, CU_TENSOR_MAP_FLOAT_OOB_FILL_NONE);
    }

    cudaFuncSetAttribute(qgemm_tc, cudaFuncAttributeMaxDynamicSharedMemorySize, SMEM_TOTAL);

    xsplit_kernel<<<(MDIM * IN_DIM + 255) / 256, 256>>>(x);
    qgemm_tc<<<OUT_DIM / NTILE, NTHREADS, SMEM_TOTAL>>>(tmA, tmB, zero, scale, bias, out);
}